// round 4
// baseline (speedup 1.0000x reference)
#include <cuda_runtime.h>
#include <stdint.h>

// CritiGraph: ct_val[t,s,c,p] = (sum_p' d - d[p] + d(cnc,pos)[c,p]) / TP
// d(a,b,norm) = sign(a)*sign(b) * (1 - e/16) * norm, e = frexp_exp(|a|^|b| + 1)
// Shapes: T=128, S=128, C=257, TP=8. Output 134.7MB fp32; L2-resident across replays
// -> latency/issue bound, not DRAM bound. Target: max occupancy + uniform warps.

#define Tn 128
#define Sn 128
#define Cn 257
#define TPn 8
#define S_CHUNK 8
#define ROW_FLOATS (Cn * TPn)   // 2056 floats per (t,s) row

__device__ __forceinline__ uint32_t packsgn(int v) {
    uint32_t a = (uint32_t)(v < 0 ? -v : v);       // |v| <= 65535
    return a | ((uint32_t)v & 0x80000000u);        // sign in bit 31
}

__device__ __forceinline__ float elem(uint32_t aw, uint32_t pw, uint32_t nsb,
                                      float fb, const float* __restrict__ lut) {
    const uint32_t tt = aw ^ pw;                   // bit31 = sign product, low16 = |a|^|b|
    const int cl = __clz(tt * 32768u + 32768u);    // clz((xor+1)<<15) -> weight idx
    const uint32_t m = nsb ^ (tt & 0x80000000u);   // sign-folded norm/8
    return fmaf(lut[cl], __uint_as_float(m), fb);
}

__global__ __launch_bounds__(256, 8)   // 256thr*32reg*8blk = 64K regs -> 100% occ
void critigraph_kernel(const int* __restrict__ sta_loc,   // (T, TP)
                       const int* __restrict__ pos_loc,   // (T, S, TP)
                       const int* __restrict__ cnc_loc,   // (T, C, TP)
                       const float* __restrict__ eu_norm, // (T, S)
                       float* __restrict__ out)           // (T, S, C, TP)
{
    __shared__ __align__(16) uint32_t sm_apw[S_CHUNK][TPn]; // |pos| | sign<<31
    __shared__ __align__(16) float    sm_fb[S_CHUNK][TPn];  // (sum - d[p]) / 8
    __shared__ uint32_t sm_nsb[S_CHUNK];                    // bits(norm/8)
    __shared__ float    sm_lut[17];                         // (idx-1)/16

    const int t   = blockIdx.x;
    const int s0  = blockIdx.y * S_CHUNK;
    const int tid = threadIdx.x;

    if (tid < 17) sm_lut[tid] = (float)(tid - 1) * 0.0625f;

    // ---- phase A: per-(s,p) constants (threads 0..63) ----
    if (tid < S_CHUNK * TPn) {
        const int sl = tid >> 3, p = tid & 7;
        const int s  = s0 + sl;
        const int pv = pos_loc[((size_t)t * Sn + s) * TPn + p];
        const uint32_t ap = (uint32_t)(pv < 0 ? -pv : pv);
        const int sv = sta_loc[t * TPn + p];
        const uint32_t as_ = (uint32_t)(sv < 0 ? -sv : sv);
        const float norm = eu_norm[t * Sn + s];

        const uint32_t x = as_ ^ ap;
        const int cl = __clz(x * 32768u + 32768u);
        float d = (float)(cl - 1) * 0.0625f * norm;
        if ((pv < 0) != (sv < 0)) d = -d;

        float sum = d;                                 // octet reduce over p
        sum += __shfl_xor_sync(0xffffffffu, sum, 1);
        sum += __shfl_xor_sync(0xffffffffu, sum, 2);
        sum += __shfl_xor_sync(0xffffffffu, sum, 4);

        sm_fb[sl][p]  = (sum - d) * 0.125f;
        sm_apw[sl][p] = ap | ((uint32_t)pv & 0x80000000u);
        if (p == 0) sm_nsb[sl] = __float_as_uint(norm * 0.125f);
    }

    // ---- register-resident cnc: thread owns vec4 columns v=tid, v=tid+256 ----
    const uint4* cnc_t = (const uint4*)(cnc_loc + (size_t)t * ROW_FLOATS);
    uint4 a0 = cnc_t[tid];
    uint4 a1 = cnc_t[tid + 256];
    a0.x = packsgn((int)a0.x); a0.y = packsgn((int)a0.y);
    a0.z = packsgn((int)a0.z); a0.w = packsgn((int)a0.w);
    a1.x = packsgn((int)a1.x); a1.y = packsgn((int)a1.y);
    a1.z = packsgn((int)a1.z); a1.w = packsgn((int)a1.w);

    // epilogue slot: 16 slots (sl 0..7 x half 0..1) on threads tid%16==0
    uint4 ae;
    const int eslot = tid >> 4;          // 0..15
    const bool edo  = (tid & 15) == 0;
    const int esl   = eslot >> 1;
    const int ehalf = eslot & 1;
    if (edo) {
        ae = cnc_t[512 + ehalf];
        ae.x = packsgn((int)ae.x); ae.y = packsgn((int)ae.y);
        ae.z = packsgn((int)ae.z); ae.w = packsgn((int)ae.w);
    }

    __syncthreads();

    // v=tid and v=tid+256 share parity -> same p-half
    const int p0 = (tid & 1) * 4;
    float* ptr = out + ((size_t)t * Sn + s0) * ROW_FLOATS + (size_t)tid * 4;

    #pragma unroll
    for (int sl = 0; sl < S_CHUNK; sl++) {
        const uint4  apw = *(const uint4*)&sm_apw[sl][p0];
        const float4 fb  = *(const float4*)&sm_fb[sl][p0];
        const uint32_t nsb = sm_nsb[sl];

        float4 r0, r1;
        r0.x = elem(a0.x, apw.x, nsb, fb.x, sm_lut);
        r0.y = elem(a0.y, apw.y, nsb, fb.y, sm_lut);
        r0.z = elem(a0.z, apw.z, nsb, fb.z, sm_lut);
        r0.w = elem(a0.w, apw.w, nsb, fb.w, sm_lut);
        r1.x = elem(a1.x, apw.x, nsb, fb.x, sm_lut);
        r1.y = elem(a1.y, apw.y, nsb, fb.y, sm_lut);
        r1.z = elem(a1.z, apw.z, nsb, fb.z, sm_lut);
        r1.w = elem(a1.w, apw.w, nsb, fb.w, sm_lut);

        __stcs((float4*)ptr, r0);
        __stcs((float4*)(ptr + 1024), r1);   // +256 float4
        ptr += ROW_FLOATS;
    }

    // ---- distributed epilogue: column c=256 (vec4 512+ehalf) for sl=esl ----
    if (edo) {
        const int ep0 = ehalf * 4;
        const uint4  apw = *(const uint4*)&sm_apw[esl][ep0];
        const float4 fb  = *(const float4*)&sm_fb[esl][ep0];
        const uint32_t nsb = sm_nsb[esl];
        float4 r;
        r.x = elem(ae.x, apw.x, nsb, fb.x, sm_lut);
        r.y = elem(ae.y, apw.y, nsb, fb.y, sm_lut);
        r.z = elem(ae.z, apw.z, nsb, fb.z, sm_lut);
        r.w = elem(ae.w, apw.w, nsb, fb.w, sm_lut);
        float* eptr = out + ((size_t)t * Sn + s0 + esl) * ROW_FLOATS
                          + (size_t)(512 + ehalf) * 4;
        __stcs((float4*)eptr, r);
    }
}

extern "C" void kernel_launch(void* const* d_in, const int* in_sizes, int n_in,
                              void* d_out, int out_size)
{
    const int*   sta = (const int*)d_in[0];
    const int*   pos = (const int*)d_in[1];
    const int*   cnc = (const int*)d_in[2];
    const float* eu  = (const float*)d_in[3];
    dim3 grid(Tn, Sn / S_CHUNK);  // (128, 16) -> 2048 blocks
    critigraph_kernel<<<grid, 256>>>(sta, pos, cnc, eu, (float*)d_out);
}

// round 5
// speedup vs baseline: 1.3113x; 1.3113x over previous
#include <cuda_runtime.h>
#include <stdint.h>

// CritiGraph: ct_val[t,s,c,p] = (sum_p' d - d[p] + d(cnc,pos)[c,p]) / TP
// d(a,b,norm) = sign(a)*sign(b) * (1 - e/16) * norm, e = frexp_exp(|a|^|b| + 1)
// weight identity: (1 - e/16)*norm/8 = e*(norm/128)*(-1)... specifically
//   lut[cl]*m8 + fb = cl*(m8/16) + (fb - m8/16), fold sign into m = ±norm/128:
//   r = fmaf(float(cl), m, fb - m)   -> no LUT, no per-element LDS.

#define Tn 128
#define Sn 128
#define Cn 257
#define TPn 8
#define S_CHUNK 16
#define ROW_FLOATS (Cn * TPn)   // 2056

__device__ __forceinline__ uint32_t packsgn(int v) {
    uint32_t a = (uint32_t)(v < 0 ? -v : v);       // |v| <= 65535
    return a | ((uint32_t)v & 0x80000000u);        // sign product lives in bit 31
}

__device__ __forceinline__ float elem(uint32_t aw, uint32_t pw, uint32_t nsb, float fb) {
    const uint32_t tt = aw ^ pw;                    // bit31 = sign product, low16 = |a|^|b|
    const int cl = __clz(tt * 32768u + 32768u);     // clz((xor+1)<<15) = 17 - e
    const float m = __uint_as_float(nsb ^ (tt & 0x80000000u));  // ±norm/128
    return fmaf((float)cl, m, fb - m);              // (cl-1)*m + fb
}

__global__ __launch_bounds__(256, 7)
void critigraph_kernel(const int* __restrict__ sta_loc,   // (T, TP)
                       const int* __restrict__ pos_loc,   // (T, S, TP)
                       const int* __restrict__ cnc_loc,   // (T, C, TP)
                       const float* __restrict__ eu_norm, // (T, S)
                       float* __restrict__ out)           // (T, S, C, TP)
{
    __shared__ __align__(16) uint32_t sm_apw[S_CHUNK][TPn]; // |pos| | sign<<31
    __shared__ __align__(16) float    sm_fb[S_CHUNK][TPn];  // (sum - d[p]) / 8
    __shared__ uint32_t sm_nsb[S_CHUNK];                    // bits(norm/128)

    const int t   = blockIdx.x;
    const int s0  = blockIdx.y * S_CHUNK;
    const int tid = threadIdx.x;

    // ---- phase A: per-(s,p) constants (threads 0..127, 4 full warps) ----
    if (tid < S_CHUNK * TPn) {
        const int sl = tid >> 3, p = tid & 7;
        const int s  = s0 + sl;
        const int pv = pos_loc[((size_t)t * Sn + s) * TPn + p];
        const uint32_t ap = (uint32_t)(pv < 0 ? -pv : pv);
        const int sv = sta_loc[t * TPn + p];
        const uint32_t as_ = (uint32_t)(sv < 0 ? -sv : sv);
        const float norm = eu_norm[t * Sn + s];

        const uint32_t x = as_ ^ ap;
        const int cl = __clz(x * 32768u + 32768u);
        float d = (float)(cl - 1) * 0.0625f * norm;
        if ((pv < 0) != (sv < 0)) d = -d;

        float sum = d;                                  // octet reduce over p
        sum += __shfl_xor_sync(0xffffffffu, sum, 1);
        sum += __shfl_xor_sync(0xffffffffu, sum, 2);
        sum += __shfl_xor_sync(0xffffffffu, sum, 4);

        sm_fb[sl][p]  = (sum - d) * 0.125f;
        sm_apw[sl][p] = ap | ((uint32_t)pv & 0x80000000u);
        if (p == 0) sm_nsb[sl] = __float_as_uint(norm * 0.0078125f);  // norm/128
    }

    // ---- register-resident cnc: thread owns vec4 columns v=tid, v=tid+256 ----
    const uint4* cnc_t = (const uint4*)(cnc_loc + (size_t)t * ROW_FLOATS);
    uint4 a0 = cnc_t[tid];
    uint4 a1 = cnc_t[tid + 256];
    a0.x = packsgn((int)a0.x); a0.y = packsgn((int)a0.y);
    a0.z = packsgn((int)a0.z); a0.w = packsgn((int)a0.w);
    a1.x = packsgn((int)a1.x); a1.y = packsgn((int)a1.y);
    a1.z = packsgn((int)a1.z); a1.w = packsgn((int)a1.w);

    // distributed epilogue: 32 slots (sl 0..15 x half 0..1) on threads tid%8==0
    uint4 ae;
    const int  eslot = tid >> 3;           // 0..31
    const bool edo   = (tid & 7) == 0;
    const int  esl   = eslot >> 1;         // 0..15
    const int  ehalf = eslot & 1;
    if (edo) {
        ae = cnc_t[512 + ehalf];
        ae.x = packsgn((int)ae.x); ae.y = packsgn((int)ae.y);
        ae.z = packsgn((int)ae.z); ae.w = packsgn((int)ae.w);
    }

    __syncthreads();

    // v=tid and v=tid+256 share parity -> same p-half for both stores
    const int p0 = (tid & 1) * 4;
    float* ptr = out + ((size_t)t * Sn + s0) * ROW_FLOATS + (size_t)tid * 4;

    #pragma unroll
    for (int sl = 0; sl < S_CHUNK; sl++) {
        const uint4  apw = *(const uint4*)&sm_apw[sl][p0];
        const float4 fb  = *(const float4*)&sm_fb[sl][p0];
        const uint32_t nsb = sm_nsb[sl];

        float4 r0, r1;
        r0.x = elem(a0.x, apw.x, nsb, fb.x);
        r0.y = elem(a0.y, apw.y, nsb, fb.y);
        r0.z = elem(a0.z, apw.z, nsb, fb.z);
        r0.w = elem(a0.w, apw.w, nsb, fb.w);
        r1.x = elem(a1.x, apw.x, nsb, fb.x);
        r1.y = elem(a1.y, apw.y, nsb, fb.y);
        r1.z = elem(a1.z, apw.z, nsb, fb.z);
        r1.w = elem(a1.w, apw.w, nsb, fb.w);

        __stcs((float4*)ptr, r0);
        __stcs((float4*)(ptr + 1024), r1);   // +256 float4
        ptr += ROW_FLOATS;
    }

    // ---- epilogue: column c=256 (vec4 index 512+ehalf) for s-line esl ----
    if (edo) {
        const int ep0 = ehalf * 4;
        const uint4  apw = *(const uint4*)&sm_apw[esl][ep0];
        const float4 fb  = *(const float4*)&sm_fb[esl][ep0];
        const uint32_t nsb = sm_nsb[esl];
        float4 r;
        r.x = elem(ae.x, apw.x, nsb, fb.x);
        r.y = elem(ae.y, apw.y, nsb, fb.y);
        r.z = elem(ae.z, apw.z, nsb, fb.z);
        r.w = elem(ae.w, apw.w, nsb, fb.w);
        float* eptr = out + ((size_t)t * Sn + s0 + esl) * ROW_FLOATS
                          + (size_t)(512 + ehalf) * 4;
        __stcs((float4*)eptr, r);
    }
}

extern "C" void kernel_launch(void* const* d_in, const int* in_sizes, int n_in,
                              void* d_out, int out_size)
{
    const int*   sta = (const int*)d_in[0];
    const int*   pos = (const int*)d_in[1];
    const int*   cnc = (const int*)d_in[2];
    const float* eu  = (const float*)d_in[3];
    dim3 grid(Tn, Sn / S_CHUNK);  // (128, 8) -> 1024 blocks
    critigraph_kernel<<<grid, 256>>>(sta, pos, cnc, eu, (float*)d_out);
}